// round 14
// baseline (speedup 1.0000x reference)
#include <cuda_runtime.h>

#define D   33
#define DD  (33 * 33)
#define NL  (33 * 33 * 33)   // 35937
#define NC  32               // cells per axis
#define NCELL (32 * 32 * 32) // 32768
#define NBASIS 8

#define Q16F   65535.0f      // stage-1 16-bit corners
#define Q11F   2047.0f       // stage-2 R,G
#define Q10F   1023.0f       // stage-2 B
#define BIASF  8388608.0f    // 2^23
#define EXPB   0x4B000000u   // float bits of 2^23

// fp32 combined LUTs (intermediate)
__device__ float4 g_clut[2][NL];
// stage-1: cell-indexed 64B records (R-cube, G-cube, B-cube, pad) -> one 128B line.
__device__ uint4  g_cube64[NCELL * 4];
// stage-2: cell-indexed 32B full-cube records (8 corners x R:11|G:11|B:10), 32B aligned.
__device__ uint4  g_cube2[NCELL * 2];

// ---------------------------------------------------------------------------
// Kernel 1: softmax-combine 8 basis LUTs (fp32), one thread per (stage,entry).
// ---------------------------------------------------------------------------
__global__ void build_clut_kernel(const float* __restrict__ lut,
                                  const float* __restrict__ lc0,
                                  const float* __restrict__ lc1) {
    int t = blockIdx.x * blockDim.x + threadIdx.x;
    if (t >= 2 * NL) return;
    int s = (t >= NL) ? 1 : 0;
    int i = t - s * NL;

    const float* lc = (s == 0) ? lc0 : lc1;
    float w[NBASIS];
    float m = -1e30f;
    #pragma unroll
    for (int n = 0; n < NBASIS; n++) m = fmaxf(m, __ldg(lc + n));
    float sum = 0.f;
    #pragma unroll
    for (int n = 0; n < NBASIS; n++) { w[n] = __expf(__ldg(lc + n) - m); sum += w[n]; }
    float inv = 1.0f / sum;

    float acc[3] = {0.f, 0.f, 0.f};
    #pragma unroll
    for (int n = 0; n < NBASIS; n++) {
        const float* basep = lut + (((size_t)s * NBASIS + n) * 3) * NL + i;
        float wn = w[n] * inv;
        #pragma unroll
        for (int c = 0; c < 3; c++)
            acc[c] = fmaf(wn, __ldg(basep + (size_t)c * NL), acc[c]);
    }
    g_clut[s][i] = make_float4(acc[0], acc[1], acc[2], 0.f);
}

// ---------------------------------------------------------------------------
// Kernel 2: pack both cell-indexed formats (one thread per cell).
// ---------------------------------------------------------------------------
__device__ __forceinline__ unsigned q16(float v) {
    v = fminf(fmaxf(v, 0.f), 1.f);
    return (unsigned)(v * Q16F + 0.5f);
}
__device__ __forceinline__ unsigned qw3(float4 c) {
    float r = fminf(fmaxf(c.x, 0.f), 1.f);
    float g = fminf(fmaxf(c.y, 0.f), 1.f);
    float b = fminf(fmaxf(c.z, 0.f), 1.f);
    return (unsigned)(r * Q11F + 0.5f)
         | ((unsigned)(g * Q11F + 0.5f) << 11)
         | ((unsigned)(b * Q10F + 0.5f) << 22);
}

__global__ void pack_cube_kernel() {
    int cidx = blockIdx.x * blockDim.x + threadIdx.x;
    if (cidx >= NCELL) return;
    int ib  = cidx >> 10;
    int ig  = (cidx >> 5) & 31;
    int ir  = cidx & 31;
    int idx = ib * DD + ig * D + ir;

    float4 c1[8], c2[8];
    #pragma unroll
    for (int k = 0; k < 8; k++) {      // corner k = di + 2*dj + 4*dk
        int off = (k & 1) + ((k >> 1) & 1) * D + ((k >> 2) & 1) * DD;
        c1[k] = g_clut[0][idx + off];
        c2[k] = g_clut[1][idx + off];
    }

    // stage-1: 64B record (R-cube, G-cube, B-cube, pad)
    uint4 uR, uG, uB;
    uR.x = q16(c1[0].x) | (q16(c1[1].x) << 16);
    uR.y = q16(c1[2].x) | (q16(c1[3].x) << 16);
    uR.z = q16(c1[4].x) | (q16(c1[5].x) << 16);
    uR.w = q16(c1[6].x) | (q16(c1[7].x) << 16);
    uG.x = q16(c1[0].y) | (q16(c1[1].y) << 16);
    uG.y = q16(c1[2].y) | (q16(c1[3].y) << 16);
    uG.z = q16(c1[4].y) | (q16(c1[5].y) << 16);
    uG.w = q16(c1[6].y) | (q16(c1[7].y) << 16);
    uB.x = q16(c1[0].z) | (q16(c1[1].z) << 16);
    uB.y = q16(c1[2].z) | (q16(c1[3].z) << 16);
    uB.z = q16(c1[4].z) | (q16(c1[5].z) << 16);
    uB.w = q16(c1[6].z) | (q16(c1[7].z) << 16);
    g_cube64[cidx * 4 + 0] = uR;
    g_cube64[cidx * 4 + 1] = uG;
    g_cube64[cidx * 4 + 2] = uB;
    g_cube64[cidx * 4 + 3] = make_uint4(0, 0, 0, 0);

    // stage-2: 32B record, halves = dk planes
    uint4 qa, qb;
    qa.x = qw3(c2[0]); qa.y = qw3(c2[1]); qa.z = qw3(c2[2]); qa.w = qw3(c2[3]);
    qb.x = qw3(c2[4]); qb.y = qw3(c2[5]); qb.z = qw3(c2[6]); qb.w = qw3(c2[7]);
    g_cube2[cidx * 2 + 0] = qa;
    g_cube2[cidx * 2 + 1] = qb;
}

// ---------------------------------------------------------------------------
// Decoders
// ---------------------------------------------------------------------------
__device__ __forceinline__ float d16lo(unsigned w) {
    return __uint_as_float(__byte_perm(w, EXPB, 0x7410));
}
__device__ __forceinline__ float d16hi(unsigned w) {
    return __uint_as_float(__byte_perm(w, EXPB, 0x7432));
}
__device__ __forceinline__ void decq(unsigned w,
                                     float& R, float& G, float& B) {
    R = __uint_as_float(EXPB | (w & 0x7FFu));
    G = __uint_as_float(EXPB | ((w >> 11) & 0x7FFu));
    B = __uint_as_float(EXPB | (w >> 22));
}

// One channel trilinear from a 16-bit cube record (BIASED result).
__device__ __forceinline__ float cube_lerp(uint4 u, float fr, float fg, float fb) {
    float c0 = d16lo(u.x), c1 = d16hi(u.x);
    float c2 = d16lo(u.y), c3 = d16hi(u.y);
    float c4 = d16lo(u.z), c5 = d16hi(u.z);
    float c6 = d16lo(u.w), c7 = d16hi(u.w);
    float a0 = fmaf(fr, c1 - c0, c0);
    float a1 = fmaf(fr, c3 - c2, c2);
    float a2 = fmaf(fr, c5 - c4, c4);
    float a3 = fmaf(fr, c7 - c6, c6);
    float b0 = fmaf(fg, a1 - a0, a0);
    float b1 = fmaf(fg, a3 - a2, a2);
    return fmaf(fb, b1 - b0, b0);
}

__device__ __forceinline__ void coords(float r, float g, float b,
                                       int& cidx, float& fr, float& fg, float& fb) {
    r = fminf(fmaxf(r, 0.f), 1.f) * (float)(D - 1);
    g = fminf(fmaxf(g, 0.f), 1.f) * (float)(D - 1);
    b = fminf(fmaxf(b, 0.f), 1.f) * (float)(D - 1);
    int ir = min((int)r, D - 2);
    int ig = min((int)g, D - 2);
    int ib = min((int)b, D - 2);
    fr = r - (float)ir;
    fg = g - (float)ig;
    fb = b - (float)ib;
    cidx = (ib << 10) | (ig << 5) | ir;
}

// Full trilinear from a 32B stage-2 cell record (qa = dk0 plane, qb = dk1 plane).
__device__ __forceinline__ float3 cell2_lerp(uint4 qa, uint4 qb,
                                             float fr, float fg, float fb) {
    float R00, G00, B00, R01, G01, B01, R10, G10, B10, R11, G11, B11;

    decq(qa.x, R00, G00, B00); decq(qa.y, R01, G01, B01);
    decq(qa.z, R10, G10, B10); decq(qa.w, R11, G11, B11);
    float ax = fmaf(fr, R01 - R00, R00);
    float ay = fmaf(fr, G01 - G00, G00);
    float az = fmaf(fr, B01 - B00, B00);
    float bx = fmaf(fr, R11 - R10, R10);
    float by = fmaf(fr, G11 - G10, G10);
    float bz = fmaf(fr, B11 - B10, B10);
    float p0x = fmaf(fg, bx - ax, ax);
    float p0y = fmaf(fg, by - ay, ay);
    float p0z = fmaf(fg, bz - az, az);

    decq(qb.x, R00, G00, B00); decq(qb.y, R01, G01, B01);
    decq(qb.z, R10, G10, B10); decq(qb.w, R11, G11, B11);
    ax = fmaf(fr, R01 - R00, R00);
    ay = fmaf(fr, G01 - G00, G00);
    az = fmaf(fr, B01 - B00, B00);
    bx = fmaf(fr, R11 - R10, R10);
    by = fmaf(fr, G11 - G10, G10);
    bz = fmaf(fr, B11 - B10, B10);
    float p1x = fmaf(fg, bx - ax, ax);
    float p1y = fmaf(fg, by - ay, ay);
    float p1z = fmaf(fg, bz - az, az);

    float tx = fmaf(fb, p1x - p0x, p0x);
    float ty = fmaf(fb, p1y - p0y, p0y);
    float tz = fmaf(fb, p1z - p0z, p0z);

    return make_float3((tx - BIASF) * (1.0f / Q11F),
                       (ty - BIASF) * (1.0f / Q11F),
                       (tz - BIASF) * (1.0f / Q10F));
}

// ---------------------------------------------------------------------------
// Kernel 3: fused apply. 2 px/thread (register relief vs R13's 4), 256-thr
// blocks. Stage-1: 4-lane coop (1 sector-access/px). Stage-2: 2-lane coop raw
// half exchange (1 sector-access/px).
// REQUIRES hw % 512 == 0 (8294400 = 16200 * 512), full warps.
// ---------------------------------------------------------------------------
#define PIX_PER_THREAD 2

__global__ __launch_bounds__(256)
void apply_lut_kernel(const float* __restrict__ gt,
                      float* __restrict__ out, int hw) {
    const unsigned FULL = 0xFFFFFFFFu;
    int t = blockIdx.x * blockDim.x + threadIdx.x;
    int base = t * PIX_PER_THREAD;
    int lane = threadIdx.x & 31;

    const float2 r2 = *reinterpret_cast<const float2*>(gt + base);
    const float2 g2 = *reinterpret_cast<const float2*>(gt + hw + base);
    const float2 b2 = *reinterpret_cast<const float2*>(gt + 2 * hw + base);

    float ri[2] = {r2.x, r2.y};
    float gi[2] = {g2.x, g2.y};
    float bi[2] = {b2.x, b2.y};
    float ro[2], go[2], bo[2];

    const int piece = lane & 3;           // stage-1: which 16B of the 64B record
    const int s0    = lane >> 2;          // stage-1: pixel-owner base (0..7)
    const int srcl  = (lane & 7) * 4;     // stage-1 redistribute source base
    const int rsel  = lane >> 3;          // stage-1: round holding my pixel
    const int half  = lane & 1;           // stage-2: which 16B half I fetch

    #pragma unroll
    for (int p = 0; p < PIX_PER_THREAD; p++) {
        // =================== STAGE 1 (4-lane coop) ===================
        int cidx; float fr, fg, fb;
        coords(ri[p], gi[p], bi[p], cidx, fr, fg, fb);

        int c0 = __shfl_sync(FULL, cidx, s0);
        int c1 = __shfl_sync(FULL, cidx, s0 + 8);
        int c2 = __shfl_sync(FULL, cidx, s0 + 16);
        int c3 = __shfl_sync(FULL, cidx, s0 + 24);
        uint4 u0 = __ldg(g_cube64 + (c0 * 4 + piece));
        uint4 u1 = __ldg(g_cube64 + (c1 * 4 + piece));
        uint4 u2 = __ldg(g_cube64 + (c2 * 4 + piece));
        uint4 u3 = __ldg(g_cube64 + (c3 * 4 + piece));

        float fra = __shfl_sync(FULL, fr, s0),      fga = __shfl_sync(FULL, fg, s0),      fba = __shfl_sync(FULL, fb, s0);
        float frb = __shfl_sync(FULL, fr, s0 + 8),  fgb = __shfl_sync(FULL, fg, s0 + 8),  fbb = __shfl_sync(FULL, fb, s0 + 8);
        float frc = __shfl_sync(FULL, fr, s0 + 16), fgc = __shfl_sync(FULL, fg, s0 + 16), fbc = __shfl_sync(FULL, fb, s0 + 16);
        float frd = __shfl_sync(FULL, fr, s0 + 24), fgd = __shfl_sync(FULL, fg, s0 + 24), fbd = __shfl_sync(FULL, fb, s0 + 24);

        float ch0 = cube_lerp(u0, fra, fga, fba);
        float ch1 = cube_lerp(u1, frb, fgb, fbb);
        float ch2 = cube_lerp(u2, frc, fgc, fbc);
        float ch3 = cube_lerp(u3, frd, fgd, fbd);

        float sv[3];
        #pragma unroll
        for (int c = 0; c < 3; c++) {
            float v0 = __shfl_sync(FULL, ch0, srcl + c);
            float v1 = __shfl_sync(FULL, ch1, srcl + c);
            float v2 = __shfl_sync(FULL, ch2, srcl + c);
            float v3 = __shfl_sync(FULL, ch3, srcl + c);
            float v  = (rsel == 0) ? v0 : (rsel == 1) ? v1 : (rsel == 2) ? v2 : v3;
            sv[c] = (v - BIASF) * (1.0f / Q16F);
        }

        // ============== STAGE 2 (2-lane coop, raw exchange) ==============
        int cidx2; float hr, hg, hb;
        coords(sv[0], sv[1], sv[2], cidx2, hr, hg, hb);

        int c_ev = __shfl_sync(FULL, cidx2, lane & ~1);        // even owner's cell
        int c_od = __shfl_sync(FULL, cidx2, (lane & ~1) | 1);  // odd owner's cell
        uint4 u_ev = __ldg(g_cube2 + (c_ev * 2 + half));
        uint4 u_od = __ldg(g_cube2 + (c_od * 2 + half));

        uint4 x_ev, x_od;
        x_ev.x = __shfl_xor_sync(FULL, u_ev.x, 1);
        x_ev.y = __shfl_xor_sync(FULL, u_ev.y, 1);
        x_ev.z = __shfl_xor_sync(FULL, u_ev.z, 1);
        x_ev.w = __shfl_xor_sync(FULL, u_ev.w, 1);
        x_od.x = __shfl_xor_sync(FULL, u_od.x, 1);
        x_od.y = __shfl_xor_sync(FULL, u_od.y, 1);
        x_od.z = __shfl_xor_sync(FULL, u_od.z, 1);
        x_od.w = __shfl_xor_sync(FULL, u_od.w, 1);

        // even lane: mine = (u_ev, x_ev); odd lane: mine = (x_od, u_od)
        uint4 qa = half ? x_od : u_ev;
        uint4 qb = half ? u_od : x_ev;

        float3 f = cell2_lerp(qa, qb, hr, hg, hb);
        ro[p] = f.x; go[p] = f.y; bo[p] = f.z;
    }

    *reinterpret_cast<float2*>(out + base)          = make_float2(ro[0], ro[1]);
    *reinterpret_cast<float2*>(out + hw + base)     = make_float2(go[0], go[1]);
    *reinterpret_cast<float2*>(out + 2 * hw + base) = make_float2(bo[0], bo[1]);
}

// ---------------------------------------------------------------------------
extern "C" void kernel_launch(void* const* d_in, const int* in_sizes, int n_in,
                              void* d_out, int out_size) {
    const float* gt  = (const float*)d_in[0];   // [3, 2160, 3840]
    const float* lut = (const float*)d_in[1];   // [2, 8, 3, 33, 33, 33]
    const float* lc0 = (const float*)d_in[2];   // [8]
    const float* lc1 = (const float*)d_in[3];   // [8]
    float* out = (float*)d_out;

    const int hw = in_sizes[0] / 3;             // 8294400 = 16200 * 512

    {
        int threads = 256;
        int blocks  = (2 * NL + threads - 1) / threads;
        build_clut_kernel<<<blocks, threads>>>(lut, lc0, lc1);
    }
    {
        int threads = 256;
        int blocks  = (NCELL + threads - 1) / threads;
        pack_cube_kernel<<<blocks, threads>>>();
    }
    {
        int threads = 256;
        int total_threads = hw / PIX_PER_THREAD;
        int blocks = total_threads / threads;   // 16200 exact
        apply_lut_kernel<<<blocks, threads>>>(gt, out, hw);
    }
}

// round 15
// speedup vs baseline: 1.0204x; 1.0204x over previous
#include <cuda_runtime.h>

#define D   33
#define DD  (33 * 33)
#define NL  (33 * 33 * 33)   // 35937
#define NC  32               // cells per axis
#define NCELL (32 * 32 * 32) // 32768
#define NBASIS 8

#define Q16F   65535.0f      // stage-1 16-bit corners
#define Q11F   2047.0f       // stage-2 R,G
#define Q10F   1023.0f       // stage-2 B
#define BIASF  8388608.0f    // 2^23
#define EXPB   0x4B000000u   // float bits of 2^23

// fp32 combined LUTs (intermediate)
__device__ float4 g_clut[2][NL];
// stage-1: cell-indexed 64B records (R-cube, G-cube, B-cube, pad) -> one 128B line.
__device__ uint4  g_cube64[NCELL * 4];
// stage-2: cell-indexed 32B full-cube records (8 corners x R:11|G:11|B:10), 32B aligned.
__device__ uint4  g_cube2[NCELL * 2];

// ---------------------------------------------------------------------------
// Kernel 1: softmax-combine 8 basis LUTs (fp32), one thread per (stage,entry).
// ---------------------------------------------------------------------------
__global__ void build_clut_kernel(const float* __restrict__ lut,
                                  const float* __restrict__ lc0,
                                  const float* __restrict__ lc1) {
    int t = blockIdx.x * blockDim.x + threadIdx.x;
    if (t >= 2 * NL) return;
    int s = (t >= NL) ? 1 : 0;
    int i = t - s * NL;

    const float* lc = (s == 0) ? lc0 : lc1;
    float w[NBASIS];
    float m = -1e30f;
    #pragma unroll
    for (int n = 0; n < NBASIS; n++) m = fmaxf(m, __ldg(lc + n));
    float sum = 0.f;
    #pragma unroll
    for (int n = 0; n < NBASIS; n++) { w[n] = __expf(__ldg(lc + n) - m); sum += w[n]; }
    float inv = 1.0f / sum;

    float acc[3] = {0.f, 0.f, 0.f};
    #pragma unroll
    for (int n = 0; n < NBASIS; n++) {
        const float* basep = lut + (((size_t)s * NBASIS + n) * 3) * NL + i;
        float wn = w[n] * inv;
        #pragma unroll
        for (int c = 0; c < 3; c++)
            acc[c] = fmaf(wn, __ldg(basep + (size_t)c * NL), acc[c]);
    }
    g_clut[s][i] = make_float4(acc[0], acc[1], acc[2], 0.f);
}

// ---------------------------------------------------------------------------
// Kernel 2: pack both cell-indexed formats (one thread per cell).
// ---------------------------------------------------------------------------
__device__ __forceinline__ unsigned q16(float v) {
    v = fminf(fmaxf(v, 0.f), 1.f);
    return (unsigned)(v * Q16F + 0.5f);
}
__device__ __forceinline__ unsigned qw3(float4 c) {
    float r = fminf(fmaxf(c.x, 0.f), 1.f);
    float g = fminf(fmaxf(c.y, 0.f), 1.f);
    float b = fminf(fmaxf(c.z, 0.f), 1.f);
    return (unsigned)(r * Q11F + 0.5f)
         | ((unsigned)(g * Q11F + 0.5f) << 11)
         | ((unsigned)(b * Q10F + 0.5f) << 22);
}

__global__ void pack_cube_kernel() {
    int cidx = blockIdx.x * blockDim.x + threadIdx.x;
    if (cidx >= NCELL) return;
    int ib  = cidx >> 10;
    int ig  = (cidx >> 5) & 31;
    int ir  = cidx & 31;
    int idx = ib * DD + ig * D + ir;

    float4 c1[8], c2[8];
    #pragma unroll
    for (int k = 0; k < 8; k++) {      // corner k = di + 2*dj + 4*dk
        int off = (k & 1) + ((k >> 1) & 1) * D + ((k >> 2) & 1) * DD;
        c1[k] = g_clut[0][idx + off];
        c2[k] = g_clut[1][idx + off];
    }

    // stage-1: 64B record (R-cube, G-cube, B-cube, pad)
    uint4 uR, uG, uB;
    uR.x = q16(c1[0].x) | (q16(c1[1].x) << 16);
    uR.y = q16(c1[2].x) | (q16(c1[3].x) << 16);
    uR.z = q16(c1[4].x) | (q16(c1[5].x) << 16);
    uR.w = q16(c1[6].x) | (q16(c1[7].x) << 16);
    uG.x = q16(c1[0].y) | (q16(c1[1].y) << 16);
    uG.y = q16(c1[2].y) | (q16(c1[3].y) << 16);
    uG.z = q16(c1[4].y) | (q16(c1[5].y) << 16);
    uG.w = q16(c1[6].y) | (q16(c1[7].y) << 16);
    uB.x = q16(c1[0].z) | (q16(c1[1].z) << 16);
    uB.y = q16(c1[2].z) | (q16(c1[3].z) << 16);
    uB.z = q16(c1[4].z) | (q16(c1[5].z) << 16);
    uB.w = q16(c1[6].z) | (q16(c1[7].z) << 16);
    g_cube64[cidx * 4 + 0] = uR;
    g_cube64[cidx * 4 + 1] = uG;
    g_cube64[cidx * 4 + 2] = uB;
    g_cube64[cidx * 4 + 3] = make_uint4(0, 0, 0, 0);

    // stage-2: 32B record, halves = dk planes
    uint4 qa, qb;
    qa.x = qw3(c2[0]); qa.y = qw3(c2[1]); qa.z = qw3(c2[2]); qa.w = qw3(c2[3]);
    qb.x = qw3(c2[4]); qb.y = qw3(c2[5]); qb.z = qw3(c2[6]); qb.w = qw3(c2[7]);
    g_cube2[cidx * 2 + 0] = qa;
    g_cube2[cidx * 2 + 1] = qb;
}

// ---------------------------------------------------------------------------
// Decoders
// ---------------------------------------------------------------------------
__device__ __forceinline__ float d16lo(unsigned w) {
    return __uint_as_float(__byte_perm(w, EXPB, 0x7410));
}
__device__ __forceinline__ float d16hi(unsigned w) {
    return __uint_as_float(__byte_perm(w, EXPB, 0x7432));
}
__device__ __forceinline__ void decq(unsigned w,
                                     float& R, float& G, float& B) {
    R = __uint_as_float(EXPB | (w & 0x7FFu));
    G = __uint_as_float(EXPB | ((w >> 11) & 0x7FFu));
    B = __uint_as_float(EXPB | (w >> 22));
}

// One channel trilinear from a 16-bit cube record (BIASED result).
__device__ __forceinline__ float cube_lerp(uint4 u, float fr, float fg, float fb) {
    float c0 = d16lo(u.x), c1 = d16hi(u.x);
    float c2 = d16lo(u.y), c3 = d16hi(u.y);
    float c4 = d16lo(u.z), c5 = d16hi(u.z);
    float c6 = d16lo(u.w), c7 = d16hi(u.w);
    float a0 = fmaf(fr, c1 - c0, c0);
    float a1 = fmaf(fr, c3 - c2, c2);
    float a2 = fmaf(fr, c5 - c4, c4);
    float a3 = fmaf(fr, c7 - c6, c6);
    float b0 = fmaf(fg, a1 - a0, a0);
    float b1 = fmaf(fg, a3 - a2, a2);
    return fmaf(fb, b1 - b0, b0);
}

__device__ __forceinline__ void coords(float r, float g, float b,
                                       int& cidx, float& fr, float& fg, float& fb) {
    r = fminf(fmaxf(r, 0.f), 1.f) * (float)(D - 1);
    g = fminf(fmaxf(g, 0.f), 1.f) * (float)(D - 1);
    b = fminf(fmaxf(b, 0.f), 1.f) * (float)(D - 1);
    int ir = min((int)r, D - 2);
    int ig = min((int)g, D - 2);
    int ib = min((int)b, D - 2);
    fr = r - (float)ir;
    fg = g - (float)ig;
    fb = b - (float)ib;
    cidx = (ib << 10) | (ig << 5) | ir;
}

// Full trilinear from a 32B stage-2 cell record (qa = dk0 plane, qb = dk1 plane).
__device__ __forceinline__ float3 cell2_lerp(uint4 qa, uint4 qb,
                                             float fr, float fg, float fb) {
    float R00, G00, B00, R01, G01, B01, R10, G10, B10, R11, G11, B11;

    decq(qa.x, R00, G00, B00); decq(qa.y, R01, G01, B01);
    decq(qa.z, R10, G10, B10); decq(qa.w, R11, G11, B11);
    float ax = fmaf(fr, R01 - R00, R00);
    float ay = fmaf(fr, G01 - G00, G00);
    float az = fmaf(fr, B01 - B00, B00);
    float bx = fmaf(fr, R11 - R10, R10);
    float by = fmaf(fr, G11 - G10, G10);
    float bz = fmaf(fr, B11 - B10, B10);
    float p0x = fmaf(fg, bx - ax, ax);
    float p0y = fmaf(fg, by - ay, ay);
    float p0z = fmaf(fg, bz - az, az);

    decq(qb.x, R00, G00, B00); decq(qb.y, R01, G01, B01);
    decq(qb.z, R10, G10, B10); decq(qb.w, R11, G11, B11);
    ax = fmaf(fr, R01 - R00, R00);
    ay = fmaf(fr, G01 - G00, G00);
    az = fmaf(fr, B01 - B00, B00);
    bx = fmaf(fr, R11 - R10, R10);
    by = fmaf(fr, G11 - G10, G10);
    bz = fmaf(fr, B11 - B10, B10);
    float p1x = fmaf(fg, bx - ax, ax);
    float p1y = fmaf(fg, by - ay, ay);
    float p1z = fmaf(fg, bz - az, az);

    float tx = fmaf(fb, p1x - p0x, p0x);
    float ty = fmaf(fb, p1y - p0y, p0y);
    float tz = fmaf(fb, p1z - p0z, p0z);

    return make_float3((tx - BIASF) * (1.0f / Q11F),
                       (ty - BIASF) * (1.0f / Q11F),
                       (tz - BIASF) * (1.0f / Q10F));
}

// ---------------------------------------------------------------------------
// Kernel 3: fused apply, 1 px/thread (lean registers -> high occupancy).
// Stage-1: 4-lane coop (1 sector/px). Stage-2: 2-lane raw exchange (1/px).
// No launch-bounds cap: let regs sit naturally (~60) for 4 blocks/SM.
// REQUIRES hw % 256 == 0 (8294400 = 32400 * 256), full warps.
// ---------------------------------------------------------------------------
__global__ __launch_bounds__(256)
void apply_lut_kernel(const float* __restrict__ gt,
                      float* __restrict__ out, int hw) {
    const unsigned FULL = 0xFFFFFFFFu;
    int t = blockIdx.x * blockDim.x + threadIdx.x;
    int lane = threadIdx.x & 31;

    float r0 = __ldg(gt + t);
    float g0 = __ldg(gt + t + hw);
    float b0 = __ldg(gt + t + 2 * hw);

    const int piece = lane & 3;           // stage-1: which 16B of the 64B record
    const int s0    = lane >> 2;          // stage-1: pixel-owner base (0..7)
    const int srcl  = (lane & 7) * 4;     // stage-1 redistribute source base
    const int rsel  = lane >> 3;          // stage-1: round holding my pixel
    const int half  = lane & 1;           // stage-2: which 16B half I fetch

    // =================== STAGE 1 (4-lane coop) ===================
    int cidx; float fr, fg, fb;
    coords(r0, g0, b0, cidx, fr, fg, fb);

    int c0 = __shfl_sync(FULL, cidx, s0);
    int c1 = __shfl_sync(FULL, cidx, s0 + 8);
    int c2 = __shfl_sync(FULL, cidx, s0 + 16);
    int c3 = __shfl_sync(FULL, cidx, s0 + 24);
    uint4 u0 = __ldg(g_cube64 + (c0 * 4 + piece));
    uint4 u1 = __ldg(g_cube64 + (c1 * 4 + piece));
    uint4 u2 = __ldg(g_cube64 + (c2 * 4 + piece));
    uint4 u3 = __ldg(g_cube64 + (c3 * 4 + piece));

    float fra = __shfl_sync(FULL, fr, s0),      fga = __shfl_sync(FULL, fg, s0),      fba = __shfl_sync(FULL, fb, s0);
    float frb = __shfl_sync(FULL, fr, s0 + 8),  fgb = __shfl_sync(FULL, fg, s0 + 8),  fbb = __shfl_sync(FULL, fb, s0 + 8);
    float frc = __shfl_sync(FULL, fr, s0 + 16), fgc = __shfl_sync(FULL, fg, s0 + 16), fbc = __shfl_sync(FULL, fb, s0 + 16);
    float frd = __shfl_sync(FULL, fr, s0 + 24), fgd = __shfl_sync(FULL, fg, s0 + 24), fbd = __shfl_sync(FULL, fb, s0 + 24);

    float ch0 = cube_lerp(u0, fra, fga, fba);
    float ch1 = cube_lerp(u1, frb, fgb, fbb);
    float ch2 = cube_lerp(u2, frc, fgc, fbc);
    float ch3 = cube_lerp(u3, frd, fgd, fbd);

    float sv[3];
    #pragma unroll
    for (int c = 0; c < 3; c++) {
        float v0 = __shfl_sync(FULL, ch0, srcl + c);
        float v1 = __shfl_sync(FULL, ch1, srcl + c);
        float v2 = __shfl_sync(FULL, ch2, srcl + c);
        float v3 = __shfl_sync(FULL, ch3, srcl + c);
        float v  = (rsel == 0) ? v0 : (rsel == 1) ? v1 : (rsel == 2) ? v2 : v3;
        sv[c] = (v - BIASF) * (1.0f / Q16F);
    }

    // ============== STAGE 2 (2-lane coop, raw exchange) ==============
    int cidx2; float hr, hg, hb;
    coords(sv[0], sv[1], sv[2], cidx2, hr, hg, hb);

    int c_ev = __shfl_sync(FULL, cidx2, lane & ~1);        // even owner's cell
    int c_od = __shfl_sync(FULL, cidx2, (lane & ~1) | 1);  // odd owner's cell
    uint4 u_ev = __ldg(g_cube2 + (c_ev * 2 + half));
    uint4 u_od = __ldg(g_cube2 + (c_od * 2 + half));

    uint4 x_ev, x_od;
    x_ev.x = __shfl_xor_sync(FULL, u_ev.x, 1);
    x_ev.y = __shfl_xor_sync(FULL, u_ev.y, 1);
    x_ev.z = __shfl_xor_sync(FULL, u_ev.z, 1);
    x_ev.w = __shfl_xor_sync(FULL, u_ev.w, 1);
    x_od.x = __shfl_xor_sync(FULL, u_od.x, 1);
    x_od.y = __shfl_xor_sync(FULL, u_od.y, 1);
    x_od.z = __shfl_xor_sync(FULL, u_od.z, 1);
    x_od.w = __shfl_xor_sync(FULL, u_od.w, 1);

    // even lane: mine = (u_ev, x_ev); odd lane: mine = (x_od, u_od)
    uint4 qa = half ? x_od : u_ev;
    uint4 qb = half ? u_od : x_ev;

    float3 f = cell2_lerp(qa, qb, hr, hg, hb);

    out[t]          = f.x;
    out[t + hw]     = f.y;
    out[t + 2 * hw] = f.z;
}

// ---------------------------------------------------------------------------
extern "C" void kernel_launch(void* const* d_in, const int* in_sizes, int n_in,
                              void* d_out, int out_size) {
    const float* gt  = (const float*)d_in[0];   // [3, 2160, 3840]
    const float* lut = (const float*)d_in[1];   // [2, 8, 3, 33, 33, 33]
    const float* lc0 = (const float*)d_in[2];   // [8]
    const float* lc1 = (const float*)d_in[3];   // [8]
    float* out = (float*)d_out;

    const int hw = in_sizes[0] / 3;             // 8294400 = 32400 * 256

    {
        int threads = 256;
        int blocks  = (2 * NL + threads - 1) / threads;
        build_clut_kernel<<<blocks, threads>>>(lut, lc0, lc1);
    }
    {
        int threads = 256;
        int blocks  = (NCELL + threads - 1) / threads;
        pack_cube_kernel<<<blocks, threads>>>();
    }
    {
        int threads = 256;
        int blocks  = hw / threads;             // 32400 exact
        apply_lut_kernel<<<blocks, threads>>>(gt, out, hw);
    }
}

// round 16
// speedup vs baseline: 1.0241x; 1.0037x over previous
#include <cuda_runtime.h>

#define D   33
#define DD  (33 * 33)
#define NL  (33 * 33 * 33)   // 35937
#define NC  32               // cells per axis
#define NCELL (32 * 32 * 32) // 32768
#define NBASIS 8

#define Q16F   65535.0f      // stage-1 16-bit corners / packed fracs
#define Q11F   2047.0f       // stage-2 R,G
#define Q10F   1023.0f       // stage-2 B
#define BIASF  8388608.0f    // 2^23
#define EXPB   0x4B000000u   // float bits of 2^23

// fp32 combined LUTs (intermediate)
__device__ float4 g_clut[2][NL];
// stage-1: cell-indexed 64B records (R-cube, G-cube, B-cube, pad) -> one 128B line.
__device__ uint4  g_cube64[NCELL * 4];
// stage-2: entry-indexed (r,g)-quad, 4 words of R:11|G:11<<11|B:10<<22 (R11 proven)
__device__ uint4  g_pack2[NL];

// ---------------------------------------------------------------------------
// Kernel 1: softmax-combine 8 basis LUTs (fp32), one thread per (stage,entry).
// ---------------------------------------------------------------------------
__global__ void build_clut_kernel(const float* __restrict__ lut,
                                  const float* __restrict__ lc0,
                                  const float* __restrict__ lc1) {
    int t = blockIdx.x * blockDim.x + threadIdx.x;
    if (t >= 2 * NL) return;
    int s = (t >= NL) ? 1 : 0;
    int i = t - s * NL;

    const float* lc = (s == 0) ? lc0 : lc1;
    float w[NBASIS];
    float m = -1e30f;
    #pragma unroll
    for (int n = 0; n < NBASIS; n++) m = fmaxf(m, __ldg(lc + n));
    float sum = 0.f;
    #pragma unroll
    for (int n = 0; n < NBASIS; n++) { w[n] = __expf(__ldg(lc + n) - m); sum += w[n]; }
    float inv = 1.0f / sum;

    float acc[3] = {0.f, 0.f, 0.f};
    #pragma unroll
    for (int n = 0; n < NBASIS; n++) {
        const float* basep = lut + (((size_t)s * NBASIS + n) * 3) * NL + i;
        float wn = w[n] * inv;
        #pragma unroll
        for (int c = 0; c < 3; c++)
            acc[c] = fmaf(wn, __ldg(basep + (size_t)c * NL), acc[c]);
    }
    g_clut[s][i] = make_float4(acc[0], acc[1], acc[2], 0.f);
}

// ---------------------------------------------------------------------------
// Kernel 2: pack both formats (one thread per LUT entry).
// ---------------------------------------------------------------------------
__device__ __forceinline__ unsigned q16v(float v) {
    v = fminf(fmaxf(v, 0.f), 1.f);
    return (unsigned)(v * Q16F + 0.5f);
}
__device__ __forceinline__ unsigned qw3(float4 c) {
    float r = fminf(fmaxf(c.x, 0.f), 1.f);
    float g = fminf(fmaxf(c.y, 0.f), 1.f);
    float b = fminf(fmaxf(c.z, 0.f), 1.f);
    return (unsigned)(r * Q11F + 0.5f)
         | ((unsigned)(g * Q11F + 0.5f) << 11)
         | ((unsigned)(b * Q10F + 0.5f) << 22);
}

__global__ void pack_clut_kernel() {
    int idx = blockIdx.x * blockDim.x + threadIdx.x;
    if (idx >= NL) return;
    int ib  = idx / DD;
    int rem = idx - ib * DD;
    int ig  = rem / D;
    int ir  = rem - ig * D;

    // stage-2 (r,g)-quad, entry-indexed
    uint4 q = make_uint4(0, 0, 0, 0);
    if (ir < D - 1 && ig < D - 1) {
        q.x = qw3(g_clut[1][idx]);
        q.y = qw3(g_clut[1][idx + 1]);
        q.z = qw3(g_clut[1][idx + D]);
        q.w = qw3(g_clut[1][idx + D + 1]);
    }
    g_pack2[idx] = q;

    // stage-1 64B cube record (valid cells: ir,ig,ib < 32)
    if (ir < D - 1 && ig < D - 1 && ib < D - 1) {
        float4 c[8];
        #pragma unroll
        for (int k = 0; k < 8; k++) {    // corner k = di + 2*dj + 4*dk
            int off = (k & 1) + ((k >> 1) & 1) * D + ((k >> 2) & 1) * DD;
            c[k] = g_clut[0][idx + off];
        }
        int cidx = (ib << 10) | (ig << 5) | ir;
        uint4 uR, uG, uB;
        uR.x = q16v(c[0].x) | (q16v(c[1].x) << 16);
        uR.y = q16v(c[2].x) | (q16v(c[3].x) << 16);
        uR.z = q16v(c[4].x) | (q16v(c[5].x) << 16);
        uR.w = q16v(c[6].x) | (q16v(c[7].x) << 16);
        uG.x = q16v(c[0].y) | (q16v(c[1].y) << 16);
        uG.y = q16v(c[2].y) | (q16v(c[3].y) << 16);
        uG.z = q16v(c[4].y) | (q16v(c[5].y) << 16);
        uG.w = q16v(c[6].y) | (q16v(c[7].y) << 16);
        uB.x = q16v(c[0].z) | (q16v(c[1].z) << 16);
        uB.y = q16v(c[2].z) | (q16v(c[3].z) << 16);
        uB.z = q16v(c[4].z) | (q16v(c[5].z) << 16);
        uB.w = q16v(c[6].z) | (q16v(c[7].z) << 16);
        g_cube64[cidx * 4 + 0] = uR;
        g_cube64[cidx * 4 + 1] = uG;
        g_cube64[cidx * 4 + 2] = uB;
        g_cube64[cidx * 4 + 3] = make_uint4(0, 0, 0, 0);
    }
}

// ---------------------------------------------------------------------------
// Decoders
// ---------------------------------------------------------------------------
__device__ __forceinline__ float d16lo(unsigned w) {
    return __uint_as_float(__byte_perm(w, EXPB, 0x7410));
}
__device__ __forceinline__ float d16hi(unsigned w) {
    return __uint_as_float(__byte_perm(w, EXPB, 0x7432));
}
__device__ __forceinline__ void decq(unsigned w,
                                     float& R, float& G, float& B) {
    R = __uint_as_float(EXPB | (w & 0x7FFu));
    G = __uint_as_float(EXPB | ((w >> 11) & 0x7FFu));
    B = __uint_as_float(EXPB | (w >> 22));
}

// One channel trilinear from a 16-bit cube record (BIASED result).
__device__ __forceinline__ float cube_lerp(uint4 u, float fr, float fg, float fb) {
    float c0 = d16lo(u.x), c1 = d16hi(u.x);
    float c2 = d16lo(u.y), c3 = d16hi(u.y);
    float c4 = d16lo(u.z), c5 = d16hi(u.z);
    float c6 = d16lo(u.w), c7 = d16hi(u.w);
    float a0 = fmaf(fr, c1 - c0, c0);
    float a1 = fmaf(fr, c3 - c2, c2);
    float a2 = fmaf(fr, c5 - c4, c4);
    float a3 = fmaf(fr, c7 - c6, c6);
    float b0 = fmaf(fg, a1 - a0, a0);
    float b1 = fmaf(fg, a3 - a2, a2);
    return fmaf(fb, b1 - b0, b0);
}

// Stage 2 (direct, R11 proven): 2 x LDG.128, entry-indexed quads.
__device__ __forceinline__ float3 lut3d_s2(float r, float g, float b) {
    r = fminf(fmaxf(r, 0.f), 1.f) * (float)(D - 1);
    g = fminf(fmaxf(g, 0.f), 1.f) * (float)(D - 1);
    b = fminf(fmaxf(b, 0.f), 1.f) * (float)(D - 1);
    int ir = min((int)r, D - 2);
    int ig = min((int)g, D - 2);
    int ib = min((int)b, D - 2);
    float fr = r - (float)ir;
    float fg = g - (float)ig;
    float fb = b - (float)ib;
    int idx = ib * DD + ig * D + ir;

    uint4 p0 = __ldg(g_pack2 + idx);
    uint4 p1 = __ldg(g_pack2 + idx + DD);

    float R00, G00, B00, R01, G01, B01, R10, G10, B10, R11, G11, B11;

    decq(p0.x, R00, G00, B00); decq(p0.y, R01, G01, B01);
    decq(p0.z, R10, G10, B10); decq(p0.w, R11, G11, B11);
    float r0x = fmaf(fr, R01 - R00, R00);
    float r0y = fmaf(fr, G01 - G00, G00);
    float r0z = fmaf(fr, B01 - B00, B00);
    float r1x = fmaf(fr, R11 - R10, R10);
    float r1y = fmaf(fr, G11 - G10, G10);
    float r1z = fmaf(fr, B11 - B10, B10);
    float p0x = fmaf(fg, r1x - r0x, r0x);
    float p0y = fmaf(fg, r1y - r0y, r0y);
    float p0z = fmaf(fg, r1z - r0z, r0z);

    decq(p1.x, R00, G00, B00); decq(p1.y, R01, G01, B01);
    decq(p1.z, R10, G10, B10); decq(p1.w, R11, G11, B11);
    r0x = fmaf(fr, R01 - R00, R00);
    r0y = fmaf(fr, G01 - G00, G00);
    r0z = fmaf(fr, B01 - B00, B00);
    r1x = fmaf(fr, R11 - R10, R10);
    r1y = fmaf(fr, G11 - G10, G10);
    r1z = fmaf(fr, B11 - B10, B10);
    float p1x = fmaf(fg, r1x - r0x, r0x);
    float p1y = fmaf(fg, r1y - r0y, r0y);
    float p1z = fmaf(fg, r1z - r0z, r0z);

    float tx = fmaf(fb, p1x - p0x, p0x);
    float ty = fmaf(fb, p1y - p0y, p0y);
    float tz = fmaf(fb, p1z - p0z, p0z);

    return make_float3((tx - BIASF) * (1.0f / Q11F),
                       (ty - BIASF) * (1.0f / Q11F),
                       (tz - BIASF) * (1.0f / Q10F));
}

// ---------------------------------------------------------------------------
// Kernel 3: fused apply (R11 structure). 4 px/thread, 256-thr blocks.
// Stage-1: 4-lane coop with PACKED owner messages (2 words instead of 4):
//   w1 = cidx(15b) | q16(fr)<<15 ; w2 = q16(fg) | q16(fb)<<16
// -> 8 broadcast shfl/round instead of 16. Stage-2: direct quad gather.
// REQUIRES hw % 1024 == 0 (8294400 = 8100 * 1024), full warps.
// ---------------------------------------------------------------------------
#define PIX_PER_THREAD 4

__global__ __launch_bounds__(256)
void apply_lut_kernel(const float* __restrict__ gt,
                      float* __restrict__ out, int hw) {
    const unsigned FULL = 0xFFFFFFFFu;
    int t = blockIdx.x * blockDim.x + threadIdx.x;
    int base = t * PIX_PER_THREAD;
    int lane = threadIdx.x & 31;

    const float4 r4 = *reinterpret_cast<const float4*>(gt + base);
    const float4 g4 = *reinterpret_cast<const float4*>(gt + hw + base);
    const float4 b4 = *reinterpret_cast<const float4*>(gt + 2 * hw + base);

    float ri[4] = {r4.x, r4.y, r4.z, r4.w};
    float gi[4] = {g4.x, g4.y, g4.z, g4.w};
    float bi[4] = {b4.x, b4.y, b4.z, b4.w};
    float ro[4], go[4], bo[4];

    const int piece = lane & 3;           // which 16B of the 64B record
    const int s0    = lane >> 2;          // pixel-owner base (0..7)
    const int srcl  = (lane & 7) * 4;     // redistribute source base
    const int rsel  = lane >> 3;          // round holding my pixel

    #pragma unroll
    for (int p = 0; p < PIX_PER_THREAD; p++) {
        // ---- stage-1 coords + packed message ----
        float rr = fminf(fmaxf(ri[p], 0.f), 1.f) * (float)(D - 1);
        float gg = fminf(fmaxf(gi[p], 0.f), 1.f) * (float)(D - 1);
        float bb = fminf(fmaxf(bi[p], 0.f), 1.f) * (float)(D - 1);
        int ir = min((int)rr, D - 2);
        int ig = min((int)gg, D - 2);
        int ib = min((int)bb, D - 2);
        unsigned qr = (unsigned)((rr - (float)ir) * Q16F + 0.5f);
        unsigned qg = (unsigned)((gg - (float)ig) * Q16F + 0.5f);
        unsigned qb = (unsigned)((bb - (float)ib) * Q16F + 0.5f);
        unsigned cidx = (unsigned)((ib << 10) | (ig << 5) | ir);
        unsigned w1 = cidx | (qr << 15);
        unsigned w2 = qg | (qb << 16);

        // ---- 8 broadcast shfl (2 words x 4 owners) ----
        unsigned w1a = __shfl_sync(FULL, w1, s0);
        unsigned w1b = __shfl_sync(FULL, w1, s0 + 8);
        unsigned w1c = __shfl_sync(FULL, w1, s0 + 16);
        unsigned w1d = __shfl_sync(FULL, w1, s0 + 24);
        unsigned w2a = __shfl_sync(FULL, w2, s0);
        unsigned w2b = __shfl_sync(FULL, w2, s0 + 8);
        unsigned w2c = __shfl_sync(FULL, w2, s0 + 16);
        unsigned w2d = __shfl_sync(FULL, w2, s0 + 24);

        // issue loads ASAP (addresses from w1 low bits)
        uint4 u0 = __ldg(g_cube64 + ((w1a & 0x7FFFu) * 4 + piece));
        uint4 u1 = __ldg(g_cube64 + ((w1b & 0x7FFFu) * 4 + piece));
        uint4 u2 = __ldg(g_cube64 + ((w1c & 0x7FFFu) * 4 + piece));
        uint4 u3 = __ldg(g_cube64 + ((w1d & 0x7FFFu) * 4 + piece));

        // decode fracs while loads are in flight
        const float sc16 = 1.0f / Q16F;
        float fra = (float)(w1a >> 15) * sc16, fga = (float)(w2a & 0xFFFFu) * sc16, fba = (float)(w2a >> 16) * sc16;
        float frb = (float)(w1b >> 15) * sc16, fgb = (float)(w2b & 0xFFFFu) * sc16, fbb = (float)(w2b >> 16) * sc16;
        float frc = (float)(w1c >> 15) * sc16, fgc = (float)(w2c & 0xFFFFu) * sc16, fbc = (float)(w2c >> 16) * sc16;
        float frd = (float)(w1d >> 15) * sc16, fgd = (float)(w2d & 0xFFFFu) * sc16, fbd = (float)(w2d >> 16) * sc16;

        float ch0 = cube_lerp(u0, fra, fga, fba);
        float ch1 = cube_lerp(u1, frb, fgb, fbb);
        float ch2 = cube_lerp(u2, frc, fgc, fbc);
        float ch3 = cube_lerp(u3, frd, fgd, fbd);

        // ---- redistribute: my channel c lives at lane srcl+c, round rsel ----
        float sv[3];
        #pragma unroll
        for (int c = 0; c < 3; c++) {
            float v0 = __shfl_sync(FULL, ch0, srcl + c);
            float v1 = __shfl_sync(FULL, ch1, srcl + c);
            float v2 = __shfl_sync(FULL, ch2, srcl + c);
            float v3 = __shfl_sync(FULL, ch3, srcl + c);
            float v  = (rsel == 0) ? v0 : (rsel == 1) ? v1 : (rsel == 2) ? v2 : v3;
            sv[c] = (v - BIASF) * (1.0f / Q16F);
        }

        // ---- stage 2 (direct gather) ----
        float3 f = lut3d_s2(sv[0], sv[1], sv[2]);
        ro[p] = f.x; go[p] = f.y; bo[p] = f.z;
    }

    *reinterpret_cast<float4*>(out + base)          = make_float4(ro[0], ro[1], ro[2], ro[3]);
    *reinterpret_cast<float4*>(out + hw + base)     = make_float4(go[0], go[1], go[2], go[3]);
    *reinterpret_cast<float4*>(out + 2 * hw + base) = make_float4(bo[0], bo[1], bo[2], bo[3]);
}

// ---------------------------------------------------------------------------
extern "C" void kernel_launch(void* const* d_in, const int* in_sizes, int n_in,
                              void* d_out, int out_size) {
    const float* gt  = (const float*)d_in[0];   // [3, 2160, 3840]
    const float* lut = (const float*)d_in[1];   // [2, 8, 3, 33, 33, 33]
    const float* lc0 = (const float*)d_in[2];   // [8]
    const float* lc1 = (const float*)d_in[3];   // [8]
    float* out = (float*)d_out;

    const int hw = in_sizes[0] / 3;             // 8294400 = 8100 * 1024

    // apply uses no smem: ask for max-L1 carveout (idempotent, capture-safe)
    cudaFuncSetAttribute(apply_lut_kernel,
                         cudaFuncAttributePreferredSharedMemoryCarveout, 0);

    {
        int threads = 256;
        int blocks  = (2 * NL + threads - 1) / threads;
        build_clut_kernel<<<blocks, threads>>>(lut, lc0, lc1);
    }
    {
        int threads = 256;
        int blocks  = (NL + threads - 1) / threads;
        pack_clut_kernel<<<blocks, threads>>>();
    }
    {
        int threads = 256;
        int total_threads = hw / PIX_PER_THREAD;
        int blocks = total_threads / threads;   // 8100 exact
        apply_lut_kernel<<<blocks, threads>>>(gt, out, hw);
    }
}

// round 17
// speedup vs baseline: 1.1000x; 1.0741x over previous
#include <cuda_runtime.h>

#define D   33
#define DD  (33 * 33)
#define NL  (33 * 33 * 33)   // 35937
#define NC  32               // cells per axis
#define NCELL (32 * 32 * 32) // 32768
#define NBASIS 8

#define Q16F   65535.0f      // stage-1 16-bit corners
#define Q11F   2047.0f      // stage-2 R,G
#define Q10F   1023.0f       // stage-2 B
#define BIASF  8388608.0f    // 2^23
#define EXPB   0x4B000000u   // float bits of 2^23

// fp32 combined LUTs (intermediate)
__device__ float4 g_clut[2][NL];
// stage-1: cell-indexed 64B records (R-cube, G-cube, B-cube, pad) -> one 128B line.
__device__ uint4  g_cube64[NCELL * 4];
// stage-2: entry-indexed (r,g)-quad, 4 words of R:11|G:11<<11|B:10<<22 (R11 proven)
__device__ uint4  g_pack2[NL];

// ---------------------------------------------------------------------------
// Kernel 1: softmax-combine 8 basis LUTs (fp32), one thread per (stage,entry).
// ---------------------------------------------------------------------------
__global__ void build_clut_kernel(const float* __restrict__ lut,
                                  const float* __restrict__ lc0,
                                  const float* __restrict__ lc1) {
    int t = blockIdx.x * blockDim.x + threadIdx.x;
    if (t >= 2 * NL) return;
    int s = (t >= NL) ? 1 : 0;
    int i = t - s * NL;

    const float* lc = (s == 0) ? lc0 : lc1;
    float w[NBASIS];
    float m = -1e30f;
    #pragma unroll
    for (int n = 0; n < NBASIS; n++) m = fmaxf(m, __ldg(lc + n));
    float sum = 0.f;
    #pragma unroll
    for (int n = 0; n < NBASIS; n++) { w[n] = __expf(__ldg(lc + n) - m); sum += w[n]; }
    float inv = 1.0f / sum;

    float acc[3] = {0.f, 0.f, 0.f};
    #pragma unroll
    for (int n = 0; n < NBASIS; n++) {
        const float* basep = lut + (((size_t)s * NBASIS + n) * 3) * NL + i;
        float wn = w[n] * inv;
        #pragma unroll
        for (int c = 0; c < 3; c++)
            acc[c] = fmaf(wn, __ldg(basep + (size_t)c * NL), acc[c]);
    }
    g_clut[s][i] = make_float4(acc[0], acc[1], acc[2], 0.f);
}

// ---------------------------------------------------------------------------
// Kernel 2: pack both formats (one thread per LUT entry).
// ---------------------------------------------------------------------------
__device__ __forceinline__ unsigned q16v(float v) {
    v = fminf(fmaxf(v, 0.f), 1.f);
    return (unsigned)(v * Q16F + 0.5f);
}
__device__ __forceinline__ unsigned qw3(float4 c) {
    float r = fminf(fmaxf(c.x, 0.f), 1.f);
    float g = fminf(fmaxf(c.y, 0.f), 1.f);
    float b = fminf(fmaxf(c.z, 0.f), 1.f);
    return (unsigned)(r * Q11F + 0.5f)
         | ((unsigned)(g * Q11F + 0.5f) << 11)
         | ((unsigned)(b * Q10F + 0.5f) << 22);
}

__global__ void pack_clut_kernel() {
    int idx = blockIdx.x * blockDim.x + threadIdx.x;
    if (idx >= NL) return;
    int ib  = idx / DD;
    int rem = idx - ib * DD;
    int ig  = rem / D;
    int ir  = rem - ig * D;

    // stage-2 (r,g)-quad, entry-indexed
    uint4 q = make_uint4(0, 0, 0, 0);
    if (ir < D - 1 && ig < D - 1) {
        q.x = qw3(g_clut[1][idx]);
        q.y = qw3(g_clut[1][idx + 1]);
        q.z = qw3(g_clut[1][idx + D]);
        q.w = qw3(g_clut[1][idx + D + 1]);
    }
    g_pack2[idx] = q;

    // stage-1 64B cube record (valid cells: ir,ig,ib < 32)
    if (ir < D - 1 && ig < D - 1 && ib < D - 1) {
        float4 c[8];
        #pragma unroll
        for (int k = 0; k < 8; k++) {    // corner k = di + 2*dj + 4*dk
            int off = (k & 1) + ((k >> 1) & 1) * D + ((k >> 2) & 1) * DD;
            c[k] = g_clut[0][idx + off];
        }
        int cidx = (ib << 10) | (ig << 5) | ir;
        uint4 uR, uG, uB;
        uR.x = q16v(c[0].x) | (q16v(c[1].x) << 16);
        uR.y = q16v(c[2].x) | (q16v(c[3].x) << 16);
        uR.z = q16v(c[4].x) | (q16v(c[5].x) << 16);
        uR.w = q16v(c[6].x) | (q16v(c[7].x) << 16);
        uG.x = q16v(c[0].y) | (q16v(c[1].y) << 16);
        uG.y = q16v(c[2].y) | (q16v(c[3].y) << 16);
        uG.z = q16v(c[4].y) | (q16v(c[5].y) << 16);
        uG.w = q16v(c[6].y) | (q16v(c[7].y) << 16);
        uB.x = q16v(c[0].z) | (q16v(c[1].z) << 16);
        uB.y = q16v(c[2].z) | (q16v(c[3].z) << 16);
        uB.z = q16v(c[4].z) | (q16v(c[5].z) << 16);
        uB.w = q16v(c[6].z) | (q16v(c[7].z) << 16);
        g_cube64[cidx * 4 + 0] = uR;
        g_cube64[cidx * 4 + 1] = uG;
        g_cube64[cidx * 4 + 2] = uB;
        g_cube64[cidx * 4 + 3] = make_uint4(0, 0, 0, 0);
    }
}

// ---------------------------------------------------------------------------
// Decoders
// ---------------------------------------------------------------------------
__device__ __forceinline__ float d16lo(unsigned w) {
    return __uint_as_float(__byte_perm(w, EXPB, 0x7410));
}
__device__ __forceinline__ float d16hi(unsigned w) {
    return __uint_as_float(__byte_perm(w, EXPB, 0x7432));
}
__device__ __forceinline__ void decq(unsigned w,
                                     float& R, float& G, float& B) {
    R = __uint_as_float(EXPB | (w & 0x7FFu));
    G = __uint_as_float(EXPB | ((w >> 11) & 0x7FFu));
    B = __uint_as_float(EXPB | (w >> 22));
}

// One channel trilinear from a 16-bit cube record (BIASED result).
__device__ __forceinline__ float cube_lerp(uint4 u, float fr, float fg, float fb) {
    float c0 = d16lo(u.x), c1 = d16hi(u.x);
    float c2 = d16lo(u.y), c3 = d16hi(u.y);
    float c4 = d16lo(u.z), c5 = d16hi(u.z);
    float c6 = d16lo(u.w), c7 = d16hi(u.w);
    float a0 = fmaf(fr, c1 - c0, c0);
    float a1 = fmaf(fr, c3 - c2, c2);
    float a2 = fmaf(fr, c5 - c4, c4);
    float a3 = fmaf(fr, c7 - c6, c6);
    float b0 = fmaf(fg, a1 - a0, a0);
    float b1 = fmaf(fg, a3 - a2, a2);
    return fmaf(fb, b1 - b0, b0);
}

// ---------------------------------------------------------------------------
// Kernel 3: fused apply, three-phase. 4 px/thread, 256-thr blocks.
// Phase 1: stage-1 4-lane coop for all 4 pixels (R11 pattern, unpacked shfl).
// Phase 2: ALL 8 stage-2 loads issued back-to-back (batched MLP).
// Phase 3: stage-2 decode/lerp + output.
// REQUIRES hw % 1024 == 0 (8294400 = 8100 * 1024), full warps.
// ---------------------------------------------------------------------------
#define PIX_PER_THREAD 4

__global__ __launch_bounds__(256)
void apply_lut_kernel(const float* __restrict__ gt,
                      float* __restrict__ out, int hw) {
    const unsigned FULL = 0xFFFFFFFFu;
    int t = blockIdx.x * blockDim.x + threadIdx.x;
    int base = t * PIX_PER_THREAD;
    int lane = threadIdx.x & 31;

    const float4 r4 = *reinterpret_cast<const float4*>(gt + base);
    const float4 g4 = *reinterpret_cast<const float4*>(gt + hw + base);
    const float4 b4 = *reinterpret_cast<const float4*>(gt + 2 * hw + base);

    float ri[4] = {r4.x, r4.y, r4.z, r4.w};
    float gi[4] = {g4.x, g4.y, g4.z, g4.w};
    float bi[4] = {b4.x, b4.y, b4.z, b4.w};

    const int piece = lane & 3;           // which 16B of the 64B record
    const int s0    = lane >> 2;          // pixel-owner base (0..7)
    const int srcl  = (lane & 7) * 4;     // redistribute source base
    const int rsel  = lane >> 3;          // round holding my pixel

    // =============== PHASE 1: stage-1 coop for all 4 pixels ===============
    float svr[4], svg[4], svb[4];

    #pragma unroll
    for (int p = 0; p < PIX_PER_THREAD; p++) {
        int cidx; float fr, fg, fb;
        {
            float rr = fminf(fmaxf(ri[p], 0.f), 1.f) * (float)(D - 1);
            float gg = fminf(fmaxf(gi[p], 0.f), 1.f) * (float)(D - 1);
            float bb = fminf(fmaxf(bi[p], 0.f), 1.f) * (float)(D - 1);
            int ir = min((int)rr, D - 2);
            int ig = min((int)gg, D - 2);
            int ib = min((int)bb, D - 2);
            fr = rr - (float)ir;
            fg = gg - (float)ig;
            fb = bb - (float)ib;
            cidx = (ib << 10) | (ig << 5) | ir;
        }

        int c0 = __shfl_sync(FULL, cidx, s0);
        int c1 = __shfl_sync(FULL, cidx, s0 + 8);
        int c2 = __shfl_sync(FULL, cidx, s0 + 16);
        int c3 = __shfl_sync(FULL, cidx, s0 + 24);
        uint4 u0 = __ldg(g_cube64 + (c0 * 4 + piece));
        uint4 u1 = __ldg(g_cube64 + (c1 * 4 + piece));
        uint4 u2 = __ldg(g_cube64 + (c2 * 4 + piece));
        uint4 u3 = __ldg(g_cube64 + (c3 * 4 + piece));

        float fra = __shfl_sync(FULL, fr, s0),      fga = __shfl_sync(FULL, fg, s0),      fba = __shfl_sync(FULL, fb, s0);
        float frb = __shfl_sync(FULL, fr, s0 + 8),  fgb = __shfl_sync(FULL, fg, s0 + 8),  fbb = __shfl_sync(FULL, fb, s0 + 8);
        float frc = __shfl_sync(FULL, fr, s0 + 16), fgc = __shfl_sync(FULL, fg, s0 + 16), fbc = __shfl_sync(FULL, fb, s0 + 16);
        float frd = __shfl_sync(FULL, fr, s0 + 24), fgd = __shfl_sync(FULL, fg, s0 + 24), fbd = __shfl_sync(FULL, fb, s0 + 24);

        float ch0 = cube_lerp(u0, fra, fga, fba);
        float ch1 = cube_lerp(u1, frb, fgb, fbb);
        float ch2 = cube_lerp(u2, frc, fgc, fbc);
        float ch3 = cube_lerp(u3, frd, fgd, fbd);

        float sv[3];
        #pragma unroll
        for (int c = 0; c < 3; c++) {
            float v0 = __shfl_sync(FULL, ch0, srcl + c);
            float v1 = __shfl_sync(FULL, ch1, srcl + c);
            float v2 = __shfl_sync(FULL, ch2, srcl + c);
            float v3 = __shfl_sync(FULL, ch3, srcl + c);
            float v  = (rsel == 0) ? v0 : (rsel == 1) ? v1 : (rsel == 2) ? v2 : v3;
            sv[c] = (v - BIASF) * (1.0f / Q16F);
        }
        svr[p] = sv[0]; svg[p] = sv[1]; svb[p] = sv[2];
    }

    // =============== PHASE 2: batch ALL stage-2 loads ===============
    float hr[4], hg[4], hb[4];
    uint4 q0[4], q1[4];

    #pragma unroll
    for (int p = 0; p < PIX_PER_THREAD; p++) {
        float rr = fminf(fmaxf(svr[p], 0.f), 1.f) * (float)(D - 1);
        float gg = fminf(fmaxf(svg[p], 0.f), 1.f) * (float)(D - 1);
        float bb = fminf(fmaxf(svb[p], 0.f), 1.f) * (float)(D - 1);
        int ir = min((int)rr, D - 2);
        int ig = min((int)gg, D - 2);
        int ib = min((int)bb, D - 2);
        hr[p] = rr - (float)ir;
        hg[p] = gg - (float)ig;
        hb[p] = bb - (float)ib;
        int idx = ib * DD + ig * D + ir;
        q0[p] = __ldg(g_pack2 + idx);
        q1[p] = __ldg(g_pack2 + idx + DD);
    }

    // =============== PHASE 3: stage-2 compute + output ===============
    float ro[4], go[4], bo[4];

    #pragma unroll
    for (int p = 0; p < PIX_PER_THREAD; p++) {
        float fr = hr[p], fg = hg[p], fb = hb[p];
        float R00, G00, B00, R01, G01, B01, R10, G10, B10, R11v, G11v, B11v;

        decq(q0[p].x, R00, G00, B00); decq(q0[p].y, R01, G01, B01);
        decq(q0[p].z, R10, G10, B10); decq(q0[p].w, R11v, G11v, B11v);
        float r0x = fmaf(fr, R01 - R00, R00);
        float r0y = fmaf(fr, G01 - G00, G00);
        float r0z = fmaf(fr, B01 - B00, B00);
        float r1x = fmaf(fr, R11v - R10, R10);
        float r1y = fmaf(fr, G11v - G10, G10);
        float r1z = fmaf(fr, B11v - B10, B10);
        float p0x = fmaf(fg, r1x - r0x, r0x);
        float p0y = fmaf(fg, r1y - r0y, r0y);
        float p0z = fmaf(fg, r1z - r0z, r0z);

        decq(q1[p].x, R00, G00, B00); decq(q1[p].y, R01, G01, B01);
        decq(q1[p].z, R10, G10, B10); decq(q1[p].w, R11v, G11v, B11v);
        r0x = fmaf(fr, R01 - R00, R00);
        r0y = fmaf(fr, G01 - G00, G00);
        r0z = fmaf(fr, B01 - B00, B00);
        r1x = fmaf(fr, R11v - R10, R10);
        r1y = fmaf(fr, G11v - G10, G10);
        r1z = fmaf(fr, B11v - B10, B10);
        float p1x = fmaf(fg, r1x - r0x, r0x);
        float p1y = fmaf(fg, r1y - r0y, r0y);
        float p1z = fmaf(fg, r1z - r0z, r0z);

        float tx = fmaf(fb, p1x - p0x, p0x);
        float ty = fmaf(fb, p1y - p0y, p0y);
        float tz = fmaf(fb, p1z - p0z, p0z);

        ro[p] = (tx - BIASF) * (1.0f / Q11F);
        go[p] = (ty - BIASF) * (1.0f / Q11F);
        bo[p] = (tz - BIASF) * (1.0f / Q10F);
    }

    *reinterpret_cast<float4*>(out + base)          = make_float4(ro[0], ro[1], ro[2], ro[3]);
    *reinterpret_cast<float4*>(out + hw + base)     = make_float4(go[0], go[1], go[2], go[3]);
    *reinterpret_cast<float4*>(out + 2 * hw + base) = make_float4(bo[0], bo[1], bo[2], bo[3]);
}

// ---------------------------------------------------------------------------
extern "C" void kernel_launch(void* const* d_in, const int* in_sizes, int n_in,
                              void* d_out, int out_size) {
    const float* gt  = (const float*)d_in[0];   // [3, 2160, 3840]
    const float* lut = (const float*)d_in[1];   // [2, 8, 3, 33, 33, 33]
    const float* lc0 = (const float*)d_in[2];   // [8]
    const float* lc1 = (const float*)d_in[3];   // [8]
    float* out = (float*)d_out;

    const int hw = in_sizes[0] / 3;             // 8294400 = 8100 * 1024

    {
        int threads = 256;
        int blocks  = (2 * NL + threads - 1) / threads;
        build_clut_kernel<<<blocks, threads>>>(lut, lc0, lc1);
    }
    {
        int threads = 256;
        int blocks  = (NL + threads - 1) / threads;
        pack_clut_kernel<<<blocks, threads>>>();
    }
    {
        int threads = 256;
        int total_threads = hw / PIX_PER_THREAD;
        int blocks = total_threads / threads;   // 8100 exact
        apply_lut_kernel<<<blocks, threads>>>(gt, out, hw);
    }
}